// round 1
// baseline (speedup 1.0000x reference)
#include <cuda_runtime.h>
#include <math.h>

#define DZ 31

static constexpr long long S0  = 31LL * 256 * 256;   // 2,031,616
static constexpr long long S1  = 31LL * 128 * 128;   //   507,904
static constexpr long long S2L = 31LL * 64 * 64;     //   126,976

// ---- scratch buffer layout (floats) ----
static constexpr long long O_CONV = 0;                      // conv output scratch (max 48*S0)
static constexpr long long O_FE   = O_CONV + 48 * S0;
static constexpr long long O_E0   = O_FE   + 16 * S0;
static constexpr long long O_E1   = O_E0   + 16 * S0;
static constexpr long long O_E2   = O_E1   + 32 * S1;
static constexpr long long O_E3   = O_E2   + 32 * S1;
static constexpr long long O_E4   = O_E3   + 64 * S2L;
static constexpr long long O_D0   = O_E4   + 64 * S2L;
static constexpr long long O_UP1  = O_D0   + 64 * S2L;      // upsample(d0+e3): 64*S1
static constexpr long long O_D1   = O_UP1  + 64 * S1;
static constexpr long long O_TMP1 = O_D1   + 32 * S1;       // d1+e2
static constexpr long long O_D2   = O_TMP1 + 32 * S1;
static constexpr long long O_UP0  = O_D2   + 32 * S1;       // upsample(d2+e1): 32*S0 (also reused for 16ch sums)
static constexpr long long O_D3   = O_UP0  + 32 * S0;
static constexpr long long O_D4   = O_D3   + 16 * S0;
static constexpr long long TOTAL  = O_D4   + 16 * S0;

__device__ float g_buf[TOTAL];

__device__ __forceinline__ float sigm(float x) { return 1.0f / (1.0f + expf(-x)); }

// ============================================================================
// Direct conv3d: 3x3x3, pad 1, depth-stride 1, H/W stride = STRIDE.
// Block: 16x16 threads = one 16x16 output tile at a fixed (co group, depth d).
// COPT output channels per thread (register accumulators).
// Weights staged in SMEM transposed [tap][co] -> LDS.128 broadcast for COPT=4.
// FLIP=1 implements deconv (kernel flipped in all 3 dims: tap k -> 26-k).
// ============================================================================
template <int COPT, int STRIDE, int FLIP>
__global__ void conv3d_kernel(const float* __restrict__ in, const float* __restrict__ w,
                              const float* __restrict__ bias, float* __restrict__ out,
                              int Ci, int Co, int Hin, int Win, int Hout, int Wout)
{
    constexpr int IT = 16 * STRIDE + 2;
    extern __shared__ float sm[];
    float* s_w  = sm;                    // Ci*27*COPT floats, layout [(ci*27+k)*COPT + j]
    float* s_in = sm + Ci * 27 * COPT;   // 3*IT*IT floats

    const int tx  = threadIdx.x, ty = threadIdx.y;
    const int tid = ty * 16 + tx;
    const int d   = blockIdx.z % DZ;
    const int co0 = (blockIdx.z / DZ) * COPT;
    const int ox0 = blockIdx.x * 16;
    const int oy0 = blockIdx.y * 16;

    // stage weights (transposed: co fastest)
    const int WCNT = Ci * 27 * COPT;
    for (int t = tid; t < WCNT; t += 256) {
        int j = t % COPT;
        int r = t / COPT;
        int k = r % 27;
        int ci = r / 27;
        int kk = FLIP ? (26 - k) : k;
        s_w[t] = w[((long long)(co0 + j) * Ci + ci) * 27 + kk];
    }

    float acc[COPT];
#pragma unroll
    for (int j = 0; j < COPT; j++) acc[j] = bias[co0 + j];

    const int gx0 = ox0 * STRIDE - 1;
    const int gy0 = oy0 * STRIDE - 1;
    const long long HWin = (long long)Hin * Win;

    for (int ci = 0; ci < Ci; ci++) {
        __syncthreads();
        const float* inc = in + (long long)ci * DZ * HWin;
        for (int t = tid; t < 3 * IT * IT; t += 256) {
            int kd = t / (IT * IT);
            int rr = (t / IT) % IT;
            int cc = t % IT;
            int gz = d - 1 + kd;
            int gy = gy0 + rr;
            int gx = gx0 + cc;
            float v = 0.0f;
            if (gz >= 0 && gz < DZ && gy >= 0 && gy < Hin && gx >= 0 && gx < Win)
                v = inc[(long long)gz * HWin + (long long)gy * Win + gx];
            s_in[t] = v;
        }
        __syncthreads();

        const float* swc = s_w + ci * 27 * COPT;
#pragma unroll
        for (int kd = 0; kd < 3; kd++)
#pragma unroll
            for (int kh = 0; kh < 3; kh++)
#pragma unroll
                for (int kw = 0; kw < 3; kw++) {
                    const int k = (kd * 3 + kh) * 3 + kw;
                    const float v = s_in[(kd * IT + ty * STRIDE + kh) * IT + tx * STRIDE + kw];
                    if (COPT == 4) {
                        float4 wv = *reinterpret_cast<const float4*>(swc + k * 4);
                        acc[0] += v * wv.x;
                        acc[1] += v * wv.y;
                        acc[2] += v * wv.z;
                        acc[3] += v * wv.w;
                    } else {
#pragma unroll
                        for (int j = 0; j < COPT; j++)
                            acc[j] += v * swc[k * COPT + j];
                    }
                }
    }

    const long long HWout = (long long)Hout * Wout;
    const int oy = oy0 + ty, ox = ox0 + tx;
#pragma unroll
    for (int j = 0; j < COPT; j++)
        out[((long long)(co0 + j) * DZ + d) * HWout + (long long)oy * Wout + ox] = acc[j];
}

// ============================================================================
// fo_pool (QRNN): gates = [2*ch][DZ][HW] (z then f). One thread per (c, hw),
// serial scan over depth (DZ=31). Loads/stores coalesced (hw contiguous).
// ============================================================================
__global__ void qrnn_kernel(const float* __restrict__ g, float* __restrict__ out,
                            int ch, long long HW, int reverse)
{
    long long idx = (long long)blockIdx.x * blockDim.x + threadIdx.x;
    if (idx >= (long long)ch * HW) return;
    int c = (int)(idx / HW);
    long long p = idx % HW;
    const float* zp = g + (long long)c * DZ * HW + p;
    const float* fp = g + (long long)(ch + c) * DZ * HW + p;
    float* op = out + (long long)c * DZ * HW + p;
    float h = 0.0f;
    if (!reverse) {
        for (int t = 0; t < DZ; t++) {
            float z = tanhf(zp[(long long)t * HW]);
            float f = sigm(fp[(long long)t * HW]);
            h = f * h + (1.0f - f) * z;
            op[(long long)t * HW] = h;
        }
    } else {
        for (int t = DZ - 1; t >= 0; t--) {
            float z = tanhf(zp[(long long)t * HW]);
            float f = sigm(fp[(long long)t * HW]);
            h = f * h + (1.0f - f) * z;
            op[(long long)t * HW] = h;
        }
    }
}

// ============================================================================
// biQRNN: gates = [3*ch][DZ][HW] (z, f1, f2). Forward scan writes, reverse scan
// accumulates; optional residual (x) added in the reverse pass.
// ============================================================================
__global__ void biqrnn_kernel(const float* __restrict__ g, const float* __restrict__ resid,
                              float* __restrict__ out, int ch, long long HW)
{
    long long idx = (long long)blockIdx.x * blockDim.x + threadIdx.x;
    if (idx >= (long long)ch * HW) return;
    int c = (int)(idx / HW);
    long long p = idx % HW;
    const float* zp = g + (long long)c * DZ * HW + p;
    const float* f1 = g + (long long)(ch + c) * DZ * HW + p;
    const float* f2 = g + (long long)(2 * ch + c) * DZ * HW + p;
    float* op = out + (long long)c * DZ * HW + p;
    const float* rp = resid ? (resid + (long long)c * DZ * HW + p) : nullptr;

    float h = 0.0f;
    for (int t = 0; t < DZ; t++) {
        float z = tanhf(zp[(long long)t * HW]);
        float f = sigm(f1[(long long)t * HW]);
        h = f * h + (1.0f - f) * z;
        op[(long long)t * HW] = h;
    }
    h = 0.0f;
    for (int t = DZ - 1; t >= 0; t--) {
        float z = tanhf(zp[(long long)t * HW]);
        float f = sigm(f2[(long long)t * HW]);
        h = f * h + (1.0f - f) * z;
        float r = rp ? rp[(long long)t * HW] : 0.0f;
        op[(long long)t * HW] += h + r;
    }
}

// out[c][d][y][x] = a[c][d][y/2][x/2] + b[c][d][y/2][x/2]   (2x nearest upsample + add)
__global__ void upadd_kernel(const float* __restrict__ a, const float* __restrict__ b,
                             float* __restrict__ out, int ch, int Hs, int Ws)
{
    long long N = (long long)ch * DZ * 4LL * Hs * Ws;
    long long i = (long long)blockIdx.x * blockDim.x + threadIdx.x;
    if (i >= N) return;
    int Wd = 2 * Ws;
    int x = (int)(i % Wd);
    long long r = i / Wd;
    int y = (int)(r % (2 * Hs));
    r /= (2 * Hs); // r = c*DZ + d
    long long src = r * ((long long)Hs * Ws) + (long long)(y >> 1) * Ws + (x >> 1);
    out[i] = a[src] + b[src];
}

__global__ void add_kernel(const float* __restrict__ a, const float* __restrict__ b,
                           float* __restrict__ o, long long n)
{
    long long i = (long long)blockIdx.x * blockDim.x + threadIdx.x;
    if (i < n) o[i] = a[i] + b[i];
}

// ============================================================================
// Host-side launch helpers
// ============================================================================
template <int COPT, int STRIDE, int FLIP>
static void conv_l(const float* in, const float* w, const float* b, float* out,
                   int Ci, int Co, int Hin, int Win)
{
    int Hout = Hin / STRIDE, Wout = Win / STRIDE;
    dim3 grid(Wout / 16, Hout / 16, (Co / COPT) * DZ);
    constexpr int IT = 16 * STRIDE + 2;
    size_t smem = (size_t)(Ci * 27 * COPT + 3 * IT * IT) * sizeof(float);
    conv3d_kernel<COPT, STRIDE, FLIP><<<grid, dim3(16, 16), smem>>>(
        in, w, b, out, Ci, Co, Hin, Win, Hout, Wout);
}

static void qrnn_l(const float* g, float* out, int ch, long long HW, int reverse)
{
    long long n = (long long)ch * HW;
    qrnn_kernel<<<(unsigned)((n + 255) / 256), 256>>>(g, out, ch, HW, reverse);
}

static void biqrnn_l(const float* g, const float* resid, float* out, int ch, long long HW)
{
    long long n = (long long)ch * HW;
    biqrnn_kernel<<<(unsigned)((n + 255) / 256), 256>>>(g, resid, out, ch, HW);
}

extern "C" void kernel_launch(void* const* d_in, const int* in_sizes, int n_in,
                              void* d_out, int out_size)
{
    (void)in_sizes; (void)n_in; (void)out_size;
    const float* x    = (const float*)d_in[0];
    const float* fe_w = (const float*)d_in[1];  const float* fe_b = (const float*)d_in[2];
    const float* e0_w = (const float*)d_in[3];  const float* e0_b = (const float*)d_in[4];
    const float* e1_w = (const float*)d_in[5];  const float* e1_b = (const float*)d_in[6];
    const float* e2_w = (const float*)d_in[7];  const float* e2_b = (const float*)d_in[8];
    const float* e3_w = (const float*)d_in[9];  const float* e3_b = (const float*)d_in[10];
    const float* e4_w = (const float*)d_in[11]; const float* e4_b = (const float*)d_in[12];
    const float* d0_w = (const float*)d_in[13]; const float* d0_b = (const float*)d_in[14];
    const float* d1_w = (const float*)d_in[15]; const float* d1_b = (const float*)d_in[16];
    const float* d2_w = (const float*)d_in[17]; const float* d2_b = (const float*)d_in[18];
    const float* d3_w = (const float*)d_in[19]; const float* d3_b = (const float*)d_in[20];
    const float* d4_w = (const float*)d_in[21]; const float* d4_b = (const float*)d_in[22];
    const float* rc_w = (const float*)d_in[23]; const float* rc_b = (const float*)d_in[24];

    void* bp = nullptr;
    cudaGetSymbolAddress(&bp, g_buf);
    float* B = (float*)bp;

    float* conv = B + O_CONV;
    float* fe   = B + O_FE;   float* e0 = B + O_E0;
    float* e1   = B + O_E1;   float* e2 = B + O_E2;
    float* e3   = B + O_E3;   float* e4 = B + O_E4;
    float* d0   = B + O_D0;   float* up1 = B + O_UP1;
    float* d1   = B + O_D1;   float* tmp1 = B + O_TMP1;
    float* d2   = B + O_D2;   float* up0 = B + O_UP0;
    float* d3   = B + O_D3;   float* d4 = B + O_D4;

    const long long HW0 = 256LL * 256, HW1 = 128LL * 128, HW2 = 64LL * 64;

    // fe = biqrnn(conv(x, 1->48))
    conv_l<4, 1, 0>(x, fe_w, fe_b, conv, 1, 48, 256, 256);
    biqrnn_l(conv, nullptr, fe, 16, HW0);

    // e0 = qrnn(conv(fe, 16->32), fwd)
    conv_l<4, 1, 0>(fe, e0_w, e0_b, conv, 16, 32, 256, 256);
    qrnn_l(conv, e0, 16, HW0, 0);

    // e1 = qrnn(conv(e0, 16->64, stride 2), rev)
    conv_l<4, 2, 0>(e0, e1_w, e1_b, conv, 16, 64, 256, 256);
    qrnn_l(conv, e1, 32, HW1, 1);

    // e2 = qrnn(conv(e1, 32->64), fwd)
    conv_l<4, 1, 0>(e1, e2_w, e2_b, conv, 32, 64, 128, 128);
    qrnn_l(conv, e2, 32, HW1, 0);

    // e3 = qrnn(conv(e2, 32->128, stride 2), rev)
    conv_l<4, 2, 0>(e2, e3_w, e3_b, conv, 32, 128, 128, 128);
    qrnn_l(conv, e3, 64, HW2, 1);

    // e4 = qrnn(conv(e3, 64->128), fwd)
    conv_l<4, 1, 0>(e3, e4_w, e4_b, conv, 64, 128, 64, 64);
    qrnn_l(conv, e4, 64, HW2, 0);

    // d0 = qrnn(deconv(e4, 64->128), rev)
    conv_l<4, 1, 1>(e4, d0_w, d0_b, conv, 64, 128, 64, 64);
    qrnn_l(conv, d0, 64, HW2, 1);

    // d1 = qrnn(conv(up2x(d0 + e3), 64->64), fwd)
    {
        long long n = 64LL * DZ * 4 * HW2;
        upadd_kernel<<<(unsigned)((n + 255) / 256), 256>>>(d0, e3, up1, 64, 64, 64);
    }
    conv_l<4, 1, 0>(up1, d1_w, d1_b, conv, 64, 64, 128, 128);
    qrnn_l(conv, d1, 32, HW1, 0);

    // d2 = qrnn(deconv(d1 + e2, 32->64), rev)
    {
        long long n = 32LL * DZ * HW1;
        add_kernel<<<(unsigned)((n + 255) / 256), 256>>>(d1, e2, tmp1, n);
    }
    conv_l<4, 1, 1>(tmp1, d2_w, d2_b, conv, 32, 64, 128, 128);
    qrnn_l(conv, d2, 32, HW1, 1);

    // d3 = qrnn(conv(up2x(d2 + e1), 32->32), fwd)
    {
        long long n = 32LL * DZ * 4 * HW1;
        upadd_kernel<<<(unsigned)((n + 255) / 256), 256>>>(d2, e1, up0, 32, 128, 128);
    }
    conv_l<4, 1, 0>(up0, d3_w, d3_b, conv, 32, 32, 256, 256);
    qrnn_l(conv, d3, 16, HW0, 0);

    // d4 = qrnn(deconv(d3 + e0, 16->32), rev)   (reuse up0 as 16ch scratch)
    {
        long long n = 16LL * DZ * HW0;
        add_kernel<<<(unsigned)((n + 255) / 256), 256>>>(d3, e0, up0, n);
    }
    conv_l<4, 1, 1>(up0, d4_w, d4_b, conv, 16, 32, 256, 256);
    qrnn_l(conv, d4, 16, HW0, 1);

    // out = biqrnn(deconv(d4 + fe, 16->3)) + x
    {
        long long n = 16LL * DZ * HW0;
        add_kernel<<<(unsigned)((n + 255) / 256), 256>>>(d4, fe, up0, n);
    }
    conv_l<3, 1, 1>(up0, rc_w, rc_b, conv, 16, 3, 256, 256);
    biqrnn_l(conv, x, (float*)d_out, 1, HW0);
}